// round 11
// baseline (speedup 1.0000x reference)
#include <cuda_runtime.h>
#include <cuda_bf16.h>
#include <math.h>

#define BATCH 8
#define NCLS  19
#define HW    (512*512)
#define NC    1000
#define DIM   768
#define FOCAL_SLOTS 256
#define QUADS_PER_B (HW/4)          // 65536
#define BLOCKS_PER_B (QUADS_PER_B/256)  // 256

// Global scratch (device globals: no allocation in kernel_launch)
__device__ float g_pred[BATCH*NCLS];
__device__ float g_inter[BATCH*NCLS];
__device__ float g_cnt[BATCH*NCLS];
__device__ float g_focal[FOCAL_SLOTS];

__global__ void zero_kernel() {
    int i = threadIdx.x;
    if (i < BATCH*NCLS) { g_pred[i] = 0.f; g_inter[i] = 0.f; g_cnt[i] = 0.f; }
    if (i < FOCAL_SLOTS) g_focal[i] = 0.f;
}

// Fused dice-partials + focal pass over seg_mask. One thread = 4 pixels (float4).
__global__ __launch_bounds__(256, 2)
void seg_kernel(const float* __restrict__ seg, const int* __restrict__ gt)
{
    __shared__ float s_pred[NCLS];
    __shared__ float s_inter[NCLS];
    __shared__ int   s_cnt[NCLS];
    __shared__ float s_focal;

    int tid = threadIdx.x;
    if (tid < NCLS) { s_pred[tid] = 0.f; s_inter[tid] = 0.f; s_cnt[tid] = 0; }
    if (tid == 0) s_focal = 0.f;
    __syncthreads();

    int b = blockIdx.x >> 8;                       // 256 blocks per batch element
    int q = ((blockIdx.x & 255) << 8) + tid;       // quad index within batch, 0..65535

    const float* base = seg + (size_t)b * NCLS * HW + (size_t)q * 4;
    float4 v[NCLS];
#pragma unroll
    for (int c = 0; c < NCLS; ++c)
        v[c] = __ldg(reinterpret_cast<const float4*>(base + (size_t)c * HW));

    int4 t4 = __ldg(reinterpret_cast<const int4*>(gt + (size_t)b * HW + (size_t)q * 4));
    int tarr[4] = { t4.x, t4.y, t4.z, t4.w };

    const float* vv = reinterpret_cast<const float*>(v);

    float facc = 0.f;
#pragma unroll
    for (int j = 0; j < 4; ++j) {
        int t = tarr[j];
        float m = -1e30f;
#pragma unroll
        for (int c = 0; c < NCLS; ++c) m = fmaxf(m, vv[c*4 + j]);
        float se = 0.f, xt = 0.f;
#pragma unroll
        for (int c = 0; c < NCLS; ++c) {
            float x = vv[c*4 + j];
            se += __expf(x - m);
            xt = (c == t) ? x : xt;                // predicated select, no dynamic reg index
        }
        float lpt = xt - m - __logf(se);           // log p_t
        float p = __expf(lpt);
        float om = 1.f - p;
        facc += 0.25f * om * om * (-lpt);          // ALPHA*(1-p)^GAMMA*ce

        atomicAdd(&s_inter[t], xt);                // dice intersection (pred at gt class)
        atomicAdd(&s_cnt[t], 1);                   // onehot sum
    }

    // per-class pred sums: warp butterfly then 1 shared atomic per warp per class
#pragma unroll
    for (int c = 0; c < NCLS; ++c) {
        float4 x = v[c];
        float a = (x.x + x.y) + (x.z + x.w);
#pragma unroll
        for (int off = 16; off > 0; off >>= 1)
            a += __shfl_xor_sync(0xffffffffu, a, off);
        if ((tid & 31) == 0) atomicAdd(&s_pred[c], a);
    }
    {
        float a = facc;
#pragma unroll
        for (int off = 16; off > 0; off >>= 1)
            a += __shfl_xor_sync(0xffffffffu, a, off);
        if ((tid & 31) == 0) atomicAdd(&s_focal, a);
    }

    __syncthreads();
    if (tid < NCLS) {
        atomicAdd(&g_pred[b*NCLS + tid],  s_pred[tid]);
        atomicAdd(&g_inter[b*NCLS + tid], s_inter[tid]);
        atomicAdd(&g_cnt[b*NCLS + tid],   (float)s_cnt[tid]);
    }
    if (tid == 32)
        atomicAdd(&g_focal[blockIdx.x & (FOCAL_SLOTS - 1)], s_focal);
}

// Single-block finalize: dice closed form, CE, modal balance, combine.
__global__ void final_kernel(const float* __restrict__ logits,
                             const int*   __restrict__ label,
                             const float* __restrict__ vis,
                             const float* __restrict__ txt,
                             const float* __restrict__ mmask,
                             const int*   __restrict__ epoch_ptr,
                             float* __restrict__ out)
{
    __shared__ float s_dice, s_ce, s_sumv, s_sumt, s_cross, s_foc;
    __shared__ float s_nv[BATCH], s_nt[BATCH];

    int tid = threadIdx.x, lane = tid & 31, wid = tid >> 5;
    if (tid == 0) { s_dice = 0.f; s_ce = 0.f; s_sumv = 0.f; s_sumt = 0.f; s_cross = 0.f; s_foc = 0.f; }
    __syncthreads();

    // dice terms: 1 - (2*inter+eps)/(pred_sum + count + eps) per (b,c)
    if (tid < BATCH*NCLS) {
        float dice = (2.f * g_inter[tid] + 1e-5f) / (g_pred[tid] + g_cnt[tid] + 1e-5f);
        atomicAdd(&s_dice, 1.f - dice);
    }
    if (tid < FOCAL_SLOTS) atomicAdd(&s_foc, g_focal[tid]);

    if (wid < BATCH) {
        // CE: warp `wid` handles logits row `wid`
        const float* row = logits + wid * NC;
        float m = -1e30f;
        for (int c = lane; c < NC; c += 32) m = fmaxf(m, row[c]);
#pragma unroll
        for (int off = 16; off > 0; off >>= 1) m = fmaxf(m, __shfl_xor_sync(0xffffffffu, m, off));
        float se = 0.f;
        for (int c = lane; c < NC; c += 32) se += __expf(row[c] - m);
#pragma unroll
        for (int off = 16; off > 0; off >>= 1) se += __shfl_xor_sync(0xffffffffu, se, off);
        if (lane == 0) {
            float lp = row[label[wid]] - m - __logf(se);
            atomicAdd(&s_ce, -lp);
        }
        // row norms for vision / text
        const float* vr = vis + wid * DIM;
        const float* tr = txt + wid * DIM;
        float sv = 0.f, st = 0.f;
        for (int d = lane; d < DIM; d += 32) {
            float a = vr[d], bb = tr[d];
            sv += a * a; st += bb * bb;
        }
#pragma unroll
        for (int off = 16; off > 0; off >>= 1) {
            sv += __shfl_xor_sync(0xffffffffu, sv, off);
            st += __shfl_xor_sync(0xffffffffu, st, off);
        }
        if (lane == 0) { s_nv[wid] = sqrtf(sv); s_nt[wid] = sqrtf(st); }
    }
    __syncthreads();

    // per-dim stats: column means of normalized features + cross term
    for (int d = tid; d < DIM; d += 256) {
        float mv = 0.f, mt = 0.f, cr = 0.f;
#pragma unroll
        for (int b = 0; b < BATCH; ++b) {
            float a = vis[b*DIM + d] / s_nv[b];
            float c = txt[b*DIM + d] / s_nt[b];
            mv += a; mt += c; cr += a * c;
        }
        mv *= 0.125f; mt *= 0.125f;
        atomicAdd(&s_sumv, mv * mv);
        atomicAdd(&s_sumt, mt * mt);
        atomicAdd(&s_cross, cr);
    }
    __syncthreads();

    if (tid == 0) {
        float ce = s_ce / (float)BATCH;
        // rows of vn are unit-norm => mean(vn^2) over (b,d) = 1/D
        float v_cons = (1.f - s_sumv) / (float)DIM;
        float t_cons = (1.f - s_sumt) / (float)DIM;
        float cross  = 1.f - s_cross / (float)BATCH;
        float m0 = 0.f, m1 = 0.f;
        for (int b = 0; b < BATCH; ++b) { m0 += mmask[2*b]; m1 += mmask[2*b + 1]; }
        m0 *= 0.125f; m1 *= 0.125f;
        int ep = epoch_ptr ? *epoch_ptr : 5;
        float beta = 0.5f * powf(0.99f, (float)ep);
        float mb = (1.f - beta) * v_cons * m0 + beta * t_cons * m1 + cross;
        float dice_loss  = s_dice / (float)(BATCH * NCLS);
        float focal_loss = s_foc / (float)((long long)BATCH * HW);
        out[0] = ce + 0.3f * mb + 0.5f * (dice_loss + focal_loss);
    }
}

extern "C" void kernel_launch(void* const* d_in, const int* in_sizes, int n_in,
                              void* d_out, int out_size)
{
    // metadata order: logits, label, vision_feat, text_feat, modal_mask, seg_mask, seg_gt, epoch
    const float* logits = (const float*)d_in[0];
    const int*   label  = (const int*)  d_in[1];
    const float* vis    = (const float*)d_in[2];
    const float* txt    = (const float*)d_in[3];
    const float* mmask  = (const float*)d_in[4];
    const float* seg    = (const float*)d_in[5];
    const int*   gt     = (const int*)  d_in[6];
    const int*   epoch  = (n_in >= 8) ? (const int*)d_in[7] : nullptr;
    float* out = (float*)d_out;

    zero_kernel<<<1, 256>>>();
    seg_kernel<<<BATCH * BLOCKS_PER_B, 256>>>(seg, gt);
    final_kernel<<<1, 256>>>(logits, label, vis, txt, mmask, epoch, out);
}